// round 2
// baseline (speedup 1.0000x reference)
#include <cuda_runtime.h>
#include <stdint.h>

// Problem constants (fixed by the reference):
//   graph_lstm_output: [B=4, S=256, C=128] float32
//   slic_output:       [B=4, H=512, W=512] int32, values in [1, S]
//   out:               [B, H, W, C] float32
//
// out[b,h,w,c] = graph[b, slic[b,h,w]-1, c]
//
// One warp per pixel: lane l loads/stores float4 covering channels [4l, 4l+4).
// Index load is a warp-uniform broadcast (single L1 transaction); the gather
// table (256*128*4B = 128 KiB per batch, 512 KiB total) is L2-resident, so
// the kernel is bounded by the 512 MiB of coalesced output stores.

static constexpr int B = 4;
static constexpr int S = 256;
static constexpr int C = 128;
static constexpr int HW = 512 * 512;
static constexpr int NPIX = B * HW;           // 1,048,576 pixels
static constexpr int WARPS_PER_BLOCK = 8;     // 256 threads
static constexpr int THREADS = WARPS_PER_BLOCK * 32;

__global__ __launch_bounds__(THREADS)
void convert2image_kernel(const float* __restrict__ graph,
                          const int*   __restrict__ slic,
                          float*       __restrict__ out) {
    const int warp_in_block = threadIdx.x >> 5;
    const int lane          = threadIdx.x & 31;

    // Each warp handles exactly one pixel; grid covers NPIX exactly
    // (NPIX % WARPS_PER_BLOCK == 0), so no bounds check needed.
    const int pix = blockIdx.x * WARPS_PER_BLOCK + warp_in_block;

    const int idx = __ldg(&slic[pix]) - 1;     // 0-based segment id (broadcast load)
    const int b   = pix >> 18;                 // pix / HW  (HW = 2^18)

    const float4* src = reinterpret_cast<const float4*>(graph + ((size_t)(b * S + idx)) * C);
    float4*       dst = reinterpret_cast<float4*>(out) + (size_t)pix * (C / 4);

    dst[lane] = __ldg(&src[lane]);
}

extern "C" void kernel_launch(void* const* d_in, const int* in_sizes, int n_in,
                              void* d_out, int out_size) {
    const float* graph = (const float*)d_in[0];   // [B, S, C] fp32
    const int*   slic  = (const int*)d_in[1];     // [B, H, W] int32
    float*       out   = (float*)d_out;           // [B, H, W, C] fp32

    const int blocks = NPIX / WARPS_PER_BLOCK;    // 131072
    convert2image_kernel<<<blocks, THREADS>>>(graph, slic, out);
}

// round 3
// speedup vs baseline: 1.3385x; 1.3385x over previous
#include <cuda_runtime.h>
#include <stdint.h>

// out[b,h,w,:] = graph[b, slic[b,h,w]-1, :]
//   graph: [B=4, S=256, C=128] fp32   (128 KiB per batch -> cached in smem)
//   slic:  [B=4, 512, 512] int32
//   out:   [B, 512, 512, 128] fp32    (512 MiB of coalesced stores = the roofline)

static constexpr int B  = 4;
static constexpr int S  = 256;
static constexpr int C  = 128;
static constexpr int HW = 512 * 512;              // 262144
static constexpr int TABLE_FLOATS = S * C;        // 32768 floats = 128 KiB
static constexpr int SMEM_BYTES   = TABLE_FLOATS * 4;

static constexpr int THREADS          = 1024;     // 32 warps
static constexpr int PIX_PER_BLOCK    = 2048;     // 64 pixels per warp
static constexpr int CHUNKS_PER_BATCH = HW / PIX_PER_BLOCK;   // 128
static constexpr int BLOCKS           = B * CHUNKS_PER_BATCH; // 512

__global__ __launch_bounds__(THREADS, 1)
void convert2image_smem_kernel(const float* __restrict__ graph,
                               const int*   __restrict__ slic,
                               float*       __restrict__ out) {
    extern __shared__ float s_table[];            // [S, C] = 128 KiB

    const int b     = blockIdx.x >> 7;            // blockIdx.x / CHUNKS_PER_BATCH
    const int chunk = blockIdx.x & (CHUNKS_PER_BATCH - 1);

    // ---- Stage the per-batch gather table into shared memory (coalesced) ----
    {
        const float4* gt = reinterpret_cast<const float4*>(graph + (size_t)b * TABLE_FLOATS);
        float4*       st = reinterpret_cast<float4*>(s_table);
        #pragma unroll
        for (int i = 0; i < TABLE_FLOATS / 4 / THREADS; i++)   // 8 iters
            st[threadIdx.x + i * THREADS] = __ldg(&gt[threadIdx.x + i * THREADS]);
    }
    __syncthreads();

    const int warp = threadIdx.x >> 5;
    const int lane = threadIdx.x & 31;

    // This warp's 64 contiguous pixels.
    const int pix0 = b * HW + chunk * PIX_PER_BLOCK + warp * 64;

    const float4* stab = reinterpret_cast<const float4*>(s_table);  // [S][32] float4
    float4*       obase = reinterpret_cast<float4*>(out);           // 32 float4 per pixel

    #pragma unroll 2
    for (int i = 0; i < 64; i += 4) {
        const int p = pix0 + i;
        // 4 segment ids in one 16B load (warp-uniform broadcast).
        const int4 iv = __ldg(reinterpret_cast<const int4*>(&slic[p]));

        // 4 independent smem gathers (LDS.128, conflict-free: lane-strided 16B).
        const float4 v0 = stab[(iv.x - 1) * 32 + lane];
        const float4 v1 = stab[(iv.y - 1) * 32 + lane];
        const float4 v2 = stab[(iv.z - 1) * 32 + lane];
        const float4 v3 = stab[(iv.w - 1) * 32 + lane];

        // 4 coalesced 512B stores.
        float4* dst = obase + (size_t)p * 32 + lane;
        dst[0]  = v0;
        dst[32] = v1;
        dst[64] = v2;
        dst[96] = v3;
    }
}

extern "C" void kernel_launch(void* const* d_in, const int* in_sizes, int n_in,
                              void* d_out, int out_size) {
    const float* graph = (const float*)d_in[0];
    const int*   slic  = (const int*)d_in[1];
    float*       out   = (float*)d_out;

    // 128 KiB dynamic smem needs an opt-in (idempotent; safe under graph capture).
    static bool attr_set = false;
    if (!attr_set) {
        cudaFuncSetAttribute(convert2image_smem_kernel,
                             cudaFuncAttributeMaxDynamicSharedMemorySize, SMEM_BYTES);
        attr_set = true;
    }

    convert2image_smem_kernel<<<BLOCKS, THREADS, SMEM_BYTES>>>(graph, slic, out);
}